// round 15
// baseline (speedup 1.0000x reference)
#include <cuda_runtime.h>
#include <math.h>

#define H        1024
#define NEXP     4
#define TPB      512                 // 16 warps; warp-per-row
#define RPB      (TPB / 32)          // 16 rows per block
#define MARGIN   0.005f              // decision-margin flag threshold (logits)
#define LN2_126  87.33654475055310898f   // 126*ln2: flush boundary offset

__global__ __launch_bounds__(TPB, 2) void moe_gate_kernel(
    const float* __restrict__ x,      // [N, 1024]
    const float* __restrict__ w,      // [4, 1024]
    float* __restrict__ out,          // [2N idx | 2N wgt | 1 aux] fp32
    int nrows)
{
    __shared__ __align__(16) float ws[NEXP * H];   // 16 KB, natural [e][k]
    {
        const float4* w4 = reinterpret_cast<const float4*>(w);
        float4* s4 = reinterpret_cast<float4*>(ws);
        for (int i = threadIdx.x; i < NEXP * H / 4; i += TPB) s4[i] = w4[i];
    }
    __syncthreads();

    const int wi   = threadIdx.x >> 5;
    const int lane = threadIdx.x & 31;
    const size_t row = (size_t)blockIdx.x * RPB + wi;
    if (row >= (size_t)nrows) return;
    const unsigned FULL = 0xffffffffu;

    // ---- stream this row: 8 independent coalesced LDG.128 ----
    const float4* xr = reinterpret_cast<const float4*>(x + row * H);
    float4 xv[8];
#pragma unroll
    for (int i = 0; i < 8; i++) xv[i] = xr[i * 32 + lane];   // 128B/line exact

    // ---- approx logits: per-lane serial partials (deterministic) ----
    const float4* w0p = reinterpret_cast<const float4*>(ws);
    const float4* w1p = reinterpret_cast<const float4*>(ws + H);
    const float4* w2p = reinterpret_cast<const float4*>(ws + 2 * H);
    const float4* w3p = reinterpret_cast<const float4*>(ws + 3 * H);
    float p0 = 0.f, p1 = 0.f, p2 = 0.f, p3 = 0.f;
#pragma unroll
    for (int i = 0; i < 8; i++) {
        int f = i * 32 + lane;
        float4 v = xv[i];
        float4 a = w0p[f], b = w1p[f], c = w2p[f], d = w3p[f];  // stride-16B, conflict-free
        p0 = fmaf(v.x, a.x, p0); p0 = fmaf(v.y, a.y, p0);
        p0 = fmaf(v.z, a.z, p0); p0 = fmaf(v.w, a.w, p0);
        p1 = fmaf(v.x, b.x, p1); p1 = fmaf(v.y, b.y, p1);
        p1 = fmaf(v.z, b.z, p1); p1 = fmaf(v.w, b.w, p1);
        p2 = fmaf(v.x, c.x, p2); p2 = fmaf(v.y, c.y, p2);
        p2 = fmaf(v.z, c.z, p2); p2 = fmaf(v.w, c.w, p2);
        p3 = fmaf(v.x, d.x, p3); p3 = fmaf(v.y, d.y, p3);
        p3 = fmaf(v.z, d.z, p3); p3 = fmaf(v.w, d.w, p3);
    }
#pragma unroll
    for (int off = 16; off > 0; off >>= 1) {   // deterministic butterfly tree
        p0 += __shfl_xor_sync(FULL, p0, off);
        p1 += __shfl_xor_sync(FULL, p1, off);
        p2 += __shfl_xor_sync(FULL, p2, off);
        p3 += __shfl_xor_sync(FULL, p3, off);
    }

    float lg[NEXP] = {p0, p1, p2, p3};
    float m = fmaxf(fmaxf(lg[0], lg[1]), fmaxf(lg[2], lg[3]));
    float g0 = lg[0] - m, g1 = lg[1] - m, g2 = lg[2] - m, g3 = lg[3] - m;

    // cheap approximate scores (for flagging + fast-path weights)
    float qf[NEXP] = {__expf(g0), __expf(g1), __expf(g2), __expf(g3)};
    float sumf = ((qf[0] + qf[1]) + qf[2]) + qf[3];

    // ---- decision-margin flags: rank gaps + flush-boundary proximity ----
    float bnd = logf(sumf) - LN2_126;   // flush boundary in g-space
    bool flag =
        fabsf(lg[0] - lg[1]) < MARGIN || fabsf(lg[0] - lg[2]) < MARGIN ||
        fabsf(lg[0] - lg[3]) < MARGIN || fabsf(lg[1] - lg[2]) < MARGIN ||
        fabsf(lg[1] - lg[3]) < MARGIN || fabsf(lg[2] - lg[3]) < MARGIN ||
        fabsf(g0 - bnd) < MARGIN || fabsf(g1 - bnd) < MARGIN ||
        fabsf(g2 - bnd) < MARGIN || fabsf(g3 - bnd) < MARGIN;

    float q[NEXP], sum;
    if (flag) {
        // ---- EXACT path (~50 rows): serial ascending chains via shfl-gather
        int e = lane & 3;
        const float4* we = reinterpret_cast<const float4*>(ws + e * H);
        float acc = 0.f;
#pragma unroll
        for (int i = 0; i < 8; i++) {
            float ax = xv[i].x, ay = xv[i].y, az = xv[i].z, aw = xv[i].w;
            for (int o = 0; o < 32; o++) {           // k ascending, bit-exact
                float bx = __shfl_sync(FULL, ax, o);
                float by = __shfl_sync(FULL, ay, o);
                float bz = __shfl_sync(FULL, az, o);
                float bw = __shfl_sync(FULL, aw, o);
                float4 wv = we[i * 32 + o];
                acc = fmaf(bx, wv.x, acc); acc = fmaf(by, wv.y, acc);
                acc = fmaf(bz, wv.z, acc); acc = fmaf(bw, wv.w, acc);
            }
        }
        #pragma unroll
        for (int k = 0; k < NEXP; k++)
            lg[k] = __shfl_sync(FULL, acc, k);       // lanes 0..3 = experts 0..3
        m = fmaxf(fmaxf(lg[0], lg[1]), fmaxf(lg[2], lg[3]));
        #pragma unroll
        for (int k = 0; k < NEXP; k++)
            q[k] = (float)exp((double)(lg[k] - m));  // frozen accurate exp
        sum = ((q[0] + q[1]) + q[2]) + q[3];
    } else {
        #pragma unroll
        for (int k = 0; k < NEXP; k++) q[k] = qf[k];
        sum = sumf;
    }

    if (lane == 0) {
        // Frozen reference-softmax contract (validated R5/R8): rn division,
        // flush denormal scores to exact 0, rank by bits, ties -> lowest idx.
        unsigned kb[NEXP];
        float sc[NEXP];
        #pragma unroll
        for (int k = 0; k < NEXP; k++) {
            float s = __fdiv_rn(q[k], sum);
            unsigned b = __float_as_uint(s);
            if (b < 0x00800000u) { b = 0u; s = 0.0f; }
            kb[k] = b; sc[k] = s;
        }
        int i0 = 0;
        #pragma unroll
        for (int k = 1; k < NEXP; k++) if (kb[k] > kb[i0]) i0 = k;
        int i1 = -1;
        #pragma unroll
        for (int k = 0; k < NEXP; k++) {
            if (k == i0) continue;
            if (i1 < 0 || kb[k] > kb[i1]) i1 = k;
        }

        float2* oidx = reinterpret_cast<float2*>(out);
        float2* owgt = reinterpret_cast<float2*>(out + 2 * (size_t)nrows);
        oidx[row] = make_float2((float)i0, (float)i1);
        owgt[row] = make_float2(sc[i0], sc[i1]);

        if (row == 0)
            out[4 * (size_t)nrows] = 0.01f;   // aux_loss == ALPHA analytically
    }
}

extern "C" void kernel_launch(void* const* d_in, const int* in_sizes, int n_in,
                              void* d_out, int out_size)
{
    const float* x = (const float*)d_in[0];   // hidden_states [8,4096,1024] fp32
    const float* w = (const float*)d_in[1];   // weight [4,1024] fp32
    float* out = (float*)d_out;

    int nrows = in_sizes[0] / H;              // 32768
    int blocks = (nrows + RPB - 1) / RPB;     // 2048
    moe_gate_kernel<<<blocks, TPB>>>(x, w, out, nrows);
}

// round 16
// speedup vs baseline: 1.0861x; 1.0861x over previous
#include <cuda_runtime.h>
#include <math.h>

#define H        1024
#define NEXP     4
#define TPB      256
#define WARPS    (TPB / 32)          // 8
#define RPW      4                   // rows per warp
#define RPB      (WARPS * RPW)       // 32 rows per block
#define MARGIN   0.005f
#define LN2_126  87.33654475055310898f

#define DOT4(ACC, V, W) \
    ACC = fmaf((V).x, (W).x, ACC); ACC = fmaf((V).y, (W).y, ACC); \
    ACC = fmaf((V).z, (W).z, ACC); ACC = fmaf((V).w, (W).w, ACC)

// Rare path (~50 rows chip-wide): bit-exact serial ascending fmaf chains
// (validated R8/R15 contract). Lanes 0..3 return experts 0..3 in lg[].
__device__ __noinline__ void exact_logits(const float* __restrict__ x,
                                          const float* __restrict__ ws,
                                          size_t row, int lane, float* lg)
{
    const unsigned FULL = 0xffffffffu;
    const float4* xr4 = reinterpret_cast<const float4*>(x + row * H);
    float4 xe[8];
#pragma unroll
    for (int i = 0; i < 8; i++) xe[i] = xr4[i * 32 + lane];

    const int e = lane & 3;
    const float4* we = reinterpret_cast<const float4*>(ws + e * H);
    float acc = 0.f;
#pragma unroll
    for (int i = 0; i < 8; i++) {
        float ax = xe[i].x, ay = xe[i].y, az = xe[i].z, aw = xe[i].w;
        for (int o = 0; o < 32; o++) {            // k ascending, bit-exact
            float bx = __shfl_sync(FULL, ax, o);
            float by = __shfl_sync(FULL, ay, o);
            float bz = __shfl_sync(FULL, az, o);
            float bw = __shfl_sync(FULL, aw, o);
            float4 wv = we[i * 32 + o];
            acc = fmaf(bx, wv.x, acc); acc = fmaf(by, wv.y, acc);
            acc = fmaf(bz, wv.z, acc); acc = fmaf(bw, wv.w, acc);
        }
    }
#pragma unroll
    for (int k = 0; k < NEXP; k++)
        lg[k] = __shfl_sync(FULL, acc, k);
}

__global__ __launch_bounds__(TPB, 3) void moe_gate_kernel(
    const float* __restrict__ x,      // [N, 1024]
    const float* __restrict__ w,      // [4, 1024]
    float* __restrict__ out,          // [2N idx | 2N wgt | 1 aux] fp32
    int nrows)
{
    __shared__ __align__(16) float ws[NEXP * H];   // 16 KB natural [e][k]
    {
        const float4* w4 = reinterpret_cast<const float4*>(w);
        float4* s4 = reinterpret_cast<float4*>(ws);
        for (int i = threadIdx.x; i < NEXP * H / 4; i += TPB) s4[i] = w4[i];
    }
    __syncthreads();

    const int wi   = threadIdx.x >> 5;
    const int lane = threadIdx.x & 31;
    const unsigned FULL = 0xffffffffu;
    const size_t rbase = (size_t)blockIdx.x * RPB + wi * RPW;
    if (rbase >= (size_t)nrows) return;

    const float4* x0 = reinterpret_cast<const float4*>(x + rbase * H);
    const float4* x1 = reinterpret_cast<const float4*>(x + (rbase + 1) * H);
    const float4* x2 = reinterpret_cast<const float4*>(x + (rbase + 2) * H);
    const float4* x3 = reinterpret_cast<const float4*>(x + (rbase + 3) * H);
    const float4* w0p = reinterpret_cast<const float4*>(ws);
    const float4* w1p = reinterpret_cast<const float4*>(ws + H);
    const float4* w2p = reinterpret_cast<const float4*>(ws + 2 * H);
    const float4* w3p = reinterpret_cast<const float4*>(ws + 3 * H);

    float4 A0 = {0,0,0,0}, A1 = {0,0,0,0}, A2 = {0,0,0,0}, A3 = {0,0,0,0};

#pragma unroll
    for (int i = 0; i < 8; i++) {
        const int f = i * 32 + lane;                 // coalesced / conflict-free
        float4 v0 = x0[f], v1 = x1[f], v2 = x2[f], v3 = x3[f];
        float4 wa = w0p[f], wb = w1p[f], wc = w2p[f], wd = w3p[f];
        DOT4(A0.x, v0, wa); DOT4(A0.y, v0, wb); DOT4(A0.z, v0, wc); DOT4(A0.w, v0, wd);
        DOT4(A1.x, v1, wa); DOT4(A1.y, v1, wb); DOT4(A1.z, v1, wc); DOT4(A1.w, v1, wd);
        DOT4(A2.x, v2, wa); DOT4(A2.y, v2, wb); DOT4(A2.z, v2, wc); DOT4(A2.w, v2, wd);
        DOT4(A3.x, v3, wa); DOT4(A3.y, v3, wb); DOT4(A3.z, v3, wc); DOT4(A3.w, v3, wd);
    }

    // deterministic butterfly (bit-identical to R15's partial scheme)
#pragma unroll
    for (int off = 16; off > 0; off >>= 1) {
        A0.x += __shfl_xor_sync(FULL, A0.x, off); A0.y += __shfl_xor_sync(FULL, A0.y, off);
        A0.z += __shfl_xor_sync(FULL, A0.z, off); A0.w += __shfl_xor_sync(FULL, A0.w, off);
        A1.x += __shfl_xor_sync(FULL, A1.x, off); A1.y += __shfl_xor_sync(FULL, A1.y, off);
        A1.z += __shfl_xor_sync(FULL, A1.z, off); A1.w += __shfl_xor_sync(FULL, A1.w, off);
        A2.x += __shfl_xor_sync(FULL, A2.x, off); A2.y += __shfl_xor_sync(FULL, A2.y, off);
        A2.z += __shfl_xor_sync(FULL, A2.z, off); A2.w += __shfl_xor_sync(FULL, A2.w, off);
        A3.x += __shfl_xor_sync(FULL, A3.x, off); A3.y += __shfl_xor_sync(FULL, A3.y, off);
        A3.z += __shfl_xor_sync(FULL, A3.z, off); A3.w += __shfl_xor_sync(FULL, A3.w, off);
    }

    float2* oidx = reinterpret_cast<float2*>(out);
    float2* owgt = reinterpret_cast<float2*>(out + 2 * (size_t)nrows);

#pragma unroll
    for (int r = 0; r < RPW; r++) {
        const size_t row = rbase + r;
        if (row >= (size_t)nrows) break;
        float4 A = (r == 0) ? A0 : (r == 1) ? A1 : (r == 2) ? A2 : A3;
        float lg[NEXP] = {A.x, A.y, A.z, A.w};

        float m = fmaxf(fmaxf(lg[0], lg[1]), fmaxf(lg[2], lg[3]));
        float g0 = lg[0] - m, g1 = lg[1] - m, g2 = lg[2] - m, g3 = lg[3] - m;
        float qf[NEXP] = {__expf(g0), __expf(g1), __expf(g2), __expf(g3)};
        float sumf = ((qf[0] + qf[1]) + qf[2]) + qf[3];

        // decision margins: rank gaps + flush-boundary proximity (warp-uniform)
        float bnd = logf(sumf) - LN2_126;
        bool flag =
            fabsf(lg[0] - lg[1]) < MARGIN || fabsf(lg[0] - lg[2]) < MARGIN ||
            fabsf(lg[0] - lg[3]) < MARGIN || fabsf(lg[1] - lg[2]) < MARGIN ||
            fabsf(lg[1] - lg[3]) < MARGIN || fabsf(lg[2] - lg[3]) < MARGIN ||
            fabsf(g0 - bnd) < MARGIN || fabsf(g1 - bnd) < MARGIN ||
            fabsf(g2 - bnd) < MARGIN || fabsf(g3 - bnd) < MARGIN;

        float q[NEXP], sum;
        if (flag) {
            float le[NEXP];
            exact_logits(x, ws, row, lane, le);      // bit-exact serial chains
            float me = fmaxf(fmaxf(le[0], le[1]), fmaxf(le[2], le[3]));
            #pragma unroll
            for (int k = 0; k < NEXP; k++)
                q[k] = (float)exp((double)(le[k] - me));   // frozen accurate exp
            sum = ((q[0] + q[1]) + q[2]) + q[3];
        } else {
            #pragma unroll
            for (int k = 0; k < NEXP; k++) q[k] = qf[k];
            sum = sumf;
        }

        if (lane == 0) {
            // Frozen reference-softmax contract (R5/R8): rn division, flush
            // denormal scores to exact 0, bit-rank, ties -> lowest index.
            unsigned kb[NEXP];
            float sc[NEXP];
            #pragma unroll
            for (int k = 0; k < NEXP; k++) {
                float s = __fdiv_rn(q[k], sum);
                unsigned b = __float_as_uint(s);
                if (b < 0x00800000u) { b = 0u; s = 0.0f; }
                kb[k] = b; sc[k] = s;
            }
            int i0 = 0;
            #pragma unroll
            for (int k = 1; k < NEXP; k++) if (kb[k] > kb[i0]) i0 = k;
            int i1 = -1;
            #pragma unroll
            for (int k = 0; k < NEXP; k++) {
                if (k == i0) continue;
                if (i1 < 0 || kb[k] > kb[i1]) i1 = k;
            }
            oidx[row] = make_float2((float)i0, (float)i1);
            owgt[row] = make_float2(sc[i0], sc[i1]);
            if (row == 0)
                out[4 * (size_t)nrows] = 0.01f;   // aux_loss == ALPHA analytically
        }
    }
}

extern "C" void kernel_launch(void* const* d_in, const int* in_sizes, int n_in,
                              void* d_out, int out_size)
{
    const float* x = (const float*)d_in[0];   // hidden_states [8,4096,1024] fp32
    const float* w = (const float*)d_in[1];   // weight [4,1024] fp32
    float* out = (float*)d_out;

    int nrows = in_sizes[0] / H;              // 32768
    int blocks = (nrows + RPB - 1) / RPB;     // 1024
    moe_gate_kernel<<<blocks, TPB>>>(x, w, out, nrows);
}